// round 8
// baseline (speedup 1.0000x reference)
#include <cuda_runtime.h>
#include <cstdint>
#include <cstddef>

#define N_NODES 50000
#define D_IN    128
#define D_HID   256
#define E_MAX   800000

// Scratch (allocation-free rule: __device__ globals)
__device__ float g_comb[N_NODES * D_HID];
__device__ float g_t1 [N_NODES * D_HID];
__device__ float g_h0 [N_NODES * D_HID];
__device__ float g_wq [262144];             // tf32-quantized, TRANSPOSED weights [n][k]
__device__ int   g_mode;
__device__ int   g_deg [N_NODES];
__device__ int   g_cur [N_NODES];
__device__ int   g_off [N_NODES + 1];
__device__ int   g_esrc[E_MAX];
__device__ int   g_bsum[256];
__device__ int   g_boff[256];

// ---------------------------------------------------------------------------
// helpers
// ---------------------------------------------------------------------------
__device__ __forceinline__ float qtf(float f) {
    uint32_t u;
    asm("cvt.rna.tf32.f32 %0, %1;" : "=r"(u) : "f"(f));
    return __uint_as_float(u);
}

__device__ __forceinline__ uint32_t smem_u32(const void* p) {
    uint32_t a;
    asm("{ .reg .u64 t; cvta.to.shared.u64 t, %1; cvt.u32.u64 %0, t; }"
        : "=r"(a) : "l"(p));
    return a;
}

__device__ __forceinline__ void cpa16(uint32_t dst, const void* src, int vbytes) {
    asm volatile("cp.async.cg.shared.global [%0], [%1], 16, %2;"
                 :: "r"(dst), "l"(src), "r"(vbytes));
}
__device__ __forceinline__ void cp_commit() {
    asm volatile("cp.async.commit_group;");
}
template<int NP>
__device__ __forceinline__ void cp_wait() {
    asm volatile("cp.async.wait_group %0;" :: "n"(NP));
}

__device__ __forceinline__ void mma8(float* c, const uint32_t* a, const uint32_t* b) {
    asm volatile(
        "mma.sync.aligned.m16n8k8.row.col.f32.tf32.tf32.f32 "
        "{%0,%1,%2,%3}, {%4,%5,%6,%7}, {%8,%9}, {%0,%1,%2,%3};\n"
        : "+f"(c[0]), "+f"(c[1]), "+f"(c[2]), "+f"(c[3])
        : "r"(a[0]), "r"(a[1]), "r"(a[2]), "r"(a[3]), "r"(b[0]), "r"(b[1]));
}

// ---------------------------------------------------------------------------
// Edge-index dtype detect (harness may deliver int64 as int32)
// ---------------------------------------------------------------------------
__global__ void detect_kernel(const void* __restrict__ ei_raw, int nscan) {
    if (threadIdx.x == 0 && blockIdx.x == 0) {
        const long long* p = (const long long*)ei_raw;
        int is64 = 1;
        for (int i = 0; i < nscan; i++) {
            long long v = p[i];
            if (v < 0 || v >= N_NODES) { is64 = 0; break; }
        }
        g_mode = is64;
    }
}

__device__ __forceinline__ int edge_at(const void* raw, long long idx) {
    return g_mode ? (int)((const long long*)raw)[idx] : ((const int*)raw)[idx];
}

// ---------------------------------------------------------------------------
// CSR build (reads raw edge buffer directly)
// ---------------------------------------------------------------------------
__global__ void zero_int_kernel(int* __restrict__ p, int n) {
    int i = blockIdx.x * blockDim.x + threadIdx.x;
    if (i < n) p[i] = 0;
}

__global__ void hist_kernel(const void* __restrict__ raw, int* __restrict__ deg, int E) {
    int e = blockIdx.x * blockDim.x + threadIdx.x;
    if (e >= E) return;
    atomicAdd(&deg[edge_at(raw, (long long)E + e)], 1);
}

#define SCAN_B 256
#define SCAN_NB ((N_NODES + SCAN_B - 1) / SCAN_B)   // 196

__global__ __launch_bounds__(SCAN_B)
void scan_p1(const int* __restrict__ deg, int* __restrict__ bsum) {
    __shared__ int sh[SCAN_B];
    int i = blockIdx.x * SCAN_B + threadIdx.x;
    sh[threadIdx.x] = (i < N_NODES) ? deg[i] : 0;
    __syncthreads();
    for (int d = SCAN_B / 2; d > 0; d >>= 1) {
        if (threadIdx.x < d) sh[threadIdx.x] += sh[threadIdx.x + d];
        __syncthreads();
    }
    if (threadIdx.x == 0) bsum[blockIdx.x] = sh[0];
}

__global__ __launch_bounds__(256)
void scan_p2(const int* __restrict__ bsum, int* __restrict__ boff) {
    __shared__ int sh[256];
    int t = threadIdx.x;
    sh[t] = (t < SCAN_NB) ? bsum[t] : 0;
    __syncthreads();
    for (int d = 1; d < 256; d <<= 1) {
        int v = (t >= d) ? sh[t - d] : 0;
        __syncthreads();
        sh[t] += v;
        __syncthreads();
    }
    if (t < SCAN_NB) boff[t] = (t == 0) ? 0 : sh[t - 1];
}

__global__ __launch_bounds__(SCAN_B)
void scan_p3(const int* __restrict__ deg, const int* __restrict__ boff,
             int* __restrict__ off, int* __restrict__ cursor) {
    __shared__ int sh[SCAN_B];
    int i = blockIdx.x * SCAN_B + threadIdx.x;
    int t = threadIdx.x;
    int v = (i < N_NODES) ? deg[i] : 0;
    sh[t] = v;
    __syncthreads();
    for (int d = 1; d < SCAN_B; d <<= 1) {
        int u = (t >= d) ? sh[t - d] : 0;
        __syncthreads();
        sh[t] += u;
        __syncthreads();
    }
    int base = boff[blockIdx.x];
    if (i < N_NODES) {
        int incl = base + sh[t];
        off[i + 1] = incl;
        cursor[i]  = incl - v;
        if (i == 0) off[0] = 0;
    }
}

__global__ void fill_kernel(const void* __restrict__ raw, int* __restrict__ cursor,
                            int* __restrict__ esrc, int E) {
    int e = blockIdx.x * blockDim.x + threadIdx.x;
    if (e >= E) return;
    int src = edge_at(raw, e);
    int dst = edge_at(raw, (long long)E + e);
    int pos = atomicAdd(&cursor[dst], 1);
    esrc[pos] = src;
}

// ---------------------------------------------------------------------------
// Weight transpose + tf32 quantize (one launch, all 5 matrices)
// dst layout per segment: [N][K], dst[n*K+k] = tf32(src[k*N+n])
// ---------------------------------------------------------------------------
__global__ void quantw_all(const float* __restrict__ w10, const float* __restrict__ w20,
                           const float* __restrict__ w11, const float* __restrict__ w21,
                           const float* __restrict__ wo,  float* __restrict__ dst) {
    int i = blockIdx.x * blockDim.x + threadIdx.x;
    if (i >= 262144) return;
    const float* src;
    int d, K, N;
    if      (i < 32768)  { src = w10; d = i;          K = 128; N = 256; }
    else if (i < 98304)  { src = w20; d = i - 32768;  K = 256; N = 256; }
    else if (i < 163840) { src = w11; d = i - 98304;  K = 256; N = 256; }
    else if (i < 229376) { src = w21; d = i - 163840; K = 256; N = 256; }
    else                 { src = wo;  d = i - 229376; K = 256; N = 128; }
    int n = d / K, k = d - n * K;
    dst[i] = qtf(src[(size_t)k * N + n]);
}

// ---------------------------------------------------------------------------
// Fused gather + GIN combine (tf32-rounded output)
// ---------------------------------------------------------------------------
__device__ __forceinline__ void f4add(float4& a, const float4& b) {
    a.x += b.x; a.y += b.y; a.z += b.z; a.w += b.w;
}
__device__ __forceinline__ float4 q4(float4 v) {
    return make_float4(qtf(v.x), qtf(v.y), qtf(v.z), qtf(v.w));
}

template<int D4>
__global__ __launch_bounds__(256)
void gather_combine(const float4* __restrict__ x,
                    const int* __restrict__ off,
                    const int* __restrict__ esrc,
                    const float* __restrict__ epsp,
                    float4* __restrict__ out) {
    int node = blockIdx.x * 8 + (threadIdx.x >> 5);
    if (node >= N_NODES) return;
    int lane = threadIdx.x & 31;
    float scale = 1.f + __ldg(epsp);
    int s = off[node], e = off[node + 1];

    float4 a0 = make_float4(0.f, 0.f, 0.f, 0.f);
    float4 a1 = make_float4(0.f, 0.f, 0.f, 0.f);

    int i = s;
    for (; i + 1 < e; i += 2) {
        const float4* r0 = x + (size_t)esrc[i]     * D4;
        const float4* r1 = x + (size_t)esrc[i + 1] * D4;
        f4add(a0, __ldg(r0 + lane));
        f4add(a0, __ldg(r1 + lane));
        if (D4 == 64) {
            f4add(a1, __ldg(r0 + lane + 32));
            f4add(a1, __ldg(r1 + lane + 32));
        }
    }
    if (i < e) {
        const float4* r0 = x + (size_t)esrc[i] * D4;
        f4add(a0, __ldg(r0 + lane));
        if (D4 == 64) f4add(a1, __ldg(r0 + lane + 32));
    }
    {
        const float4* sp = x + (size_t)node * D4;
        float4 v = __ldg(sp + lane);
        a0.x = fmaf(scale, v.x, a0.x);
        a0.y = fmaf(scale, v.y, a0.y);
        a0.z = fmaf(scale, v.z, a0.z);
        a0.w = fmaf(scale, v.w, a0.w);
        if (D4 == 64) {
            float4 w = __ldg(sp + lane + 32);
            a1.x = fmaf(scale, w.x, a1.x);
            a1.y = fmaf(scale, w.y, a1.y);
            a1.z = fmaf(scale, w.z, a1.z);
            a1.w = fmaf(scale, w.w, a1.w);
        }
    }
    out[(size_t)node * D4 + lane] = q4(a0);
    if (D4 == 64) out[(size_t)node * D4 + lane + 32] = q4(a1);
}

// ---------------------------------------------------------------------------
// TF32 mma.sync GEMM, 3-stage cp.async pipeline, float2 fragment loads.
//   C = op(A @ Wt^T + bias);  BM=128, BN=128, BK=32; 256 thr (4m x 2n warps).
//   A smem [m][32] XOR-swizzled; B smem [n][32] XOR-swizzled (Wt is [n][k]).
//   Fragment trick: float2 at physical cols (2t,2t+1) maps to frag-k (t,t+4)
//   identically for A and B, so the implicit k-permutation cancels.
// ---------------------------------------------------------------------------
#define ASTAGE 4096                // floats (128 rows x 32)
#define BSTAGE 4096                // floats (128 rows x 32)
#define STG    (ASTAGE + BSTAGE)
#define GEMM_SMEM_BYTES (3 * STG * 4)

// swizzled float index for (row, u8) where u8 = 8-byte unit index 0..15
__device__ __forceinline__ int swz_idx(int row, int u8) {
    return row * 32 + ((u8 ^ ((row & 3) << 2)) << 1);
}

template<bool RELU, bool QUANT>
__global__ __launch_bounds__(256, 2)
void gemm_cp(const float* __restrict__ A,
             const float* __restrict__ Wt,     // [Ntot][K]
             const float* __restrict__ bias,
             float* __restrict__ C,
             int M, int K, int Ncol) {
    extern __shared__ float dsm[];
    const uint32_t sbase = smem_u32(dsm);

    const int tid  = threadIdx.x;
    const int lane = tid & 31;
    const int warp = tid >> 5;
    const int wm   = warp >> 1;        // 0..3
    const int wn   = warp & 1;         // 0..1
    const int gid  = lane >> 2;        // 0..7
    const int tig  = lane & 3;         // 0..3

    const int row0 = blockIdx.x * 128;
    const int col0 = blockIdx.y * 128;

    float acc[2][8][4];
    #pragma unroll
    for (int mt = 0; mt < 2; mt++)
        #pragma unroll
        for (int nt = 0; nt < 8; nt++)
            #pragma unroll
            for (int i = 0; i < 4; i++)
                acc[mt][nt][i] = 0.f;

    auto issue = [&](int c) {
        const int k0  = c * 32;
        const int stg = c % 3;
        const uint32_t abase = sbase + (stg * STG) * 4;
        #pragma unroll
        for (int i = 0; i < 4; i++) {
            int chunk = tid + 256 * i;          // 0..1023
            int row = chunk >> 3, c16 = chunk & 7;
            bool ok = (row0 + row) < M;
            const float* src = ok ? (A + (size_t)(row0 + row) * K + k0 + c16 * 4) : A;
            cpa16(abase + swz_idx(row, c16 * 2) * 4, src, ok ? 16 : 0);
        }
        const uint32_t bbase = abase + ASTAGE * 4;
        #pragma unroll
        for (int i = 0; i < 4; i++) {
            int chunk = tid + 256 * i;          // 0..1023
            int n = chunk >> 3, c16 = chunk & 7;
            const float* src = Wt + (size_t)(col0 + n) * K + k0 + c16 * 4;
            cpa16(bbase + swz_idx(n, c16 * 2) * 4, src, 16);
        }
    };

    auto compute = [&](int c) {
        const int stg = c % 3;
        const float* As = dsm + stg * STG;
        const float* Bs = As + ASTAGE;
        #pragma unroll
        for (int ks = 0; ks < 4; ks++) {
            const int u = ks * 4 + tig;        // 8-byte unit within row
            uint32_t af[2][4];
            #pragma unroll
            for (int mt = 0; mt < 2; mt++) {
                int r = wm * 32 + mt * 16 + gid;
                float2 a01 = *reinterpret_cast<const float2*>(&As[swz_idx(r,     u)]);
                float2 a23 = *reinterpret_cast<const float2*>(&As[swz_idx(r + 8, u)]);
                af[mt][0] = __float_as_uint(a01.x);
                af[mt][1] = __float_as_uint(a23.x);
                af[mt][2] = __float_as_uint(a01.y);
                af[mt][3] = __float_as_uint(a23.y);
            }
            uint32_t bf[8][2];
            #pragma unroll
            for (int nt = 0; nt < 8; nt++) {
                int n = wn * 64 + nt * 8 + gid;
                float2 b01 = *reinterpret_cast<const float2*>(&Bs[swz_idx(n, u)]);
                bf[nt][0] = __float_as_uint(b01.x);
                bf[nt][1] = __float_as_uint(b01.y);
            }
            #pragma unroll
            for (int mt = 0; mt < 2; mt++)
                #pragma unroll
                for (int nt = 0; nt < 8; nt++)
                    mma8(acc[mt][nt], af[mt], bf[nt]);
        }
    };

    const int NC = K / 32;
    issue(0); cp_commit();
    issue(1); cp_commit();

    for (int c = 0; c < NC; c++) {
        cp_wait<1>();
        __syncthreads();
        if (c + 2 < NC) issue(c + 2);
        cp_commit();
        compute(c);
    }

    // ---- epilogue ----
    #pragma unroll
    for (int nt = 0; nt < 8; nt++) {
        int col = col0 + wn * 64 + nt * 8 + 2 * tig;
        float b0 = __ldg(bias + col);
        float b1 = __ldg(bias + col + 1);
        #pragma unroll
        for (int mt = 0; mt < 2; mt++) {
            int r = row0 + wm * 32 + mt * 16 + gid;
            float v0 = acc[mt][nt][0] + b0;
            float v1 = acc[mt][nt][1] + b1;
            float v2 = acc[mt][nt][2] + b0;
            float v3 = acc[mt][nt][3] + b1;
            if (RELU) {
                v0 = fmaxf(v0, 0.f); v1 = fmaxf(v1, 0.f);
                v2 = fmaxf(v2, 0.f); v3 = fmaxf(v3, 0.f);
            }
            if (QUANT) {
                v0 = qtf(v0); v1 = qtf(v1); v2 = qtf(v2); v3 = qtf(v3);
            }
            if (r < M)
                *reinterpret_cast<float2*>(C + (size_t)r * Ncol + col) = make_float2(v0, v1);
            if (r + 8 < M)
                *reinterpret_cast<float2*>(C + (size_t)(r + 8) * Ncol + col) = make_float2(v2, v3);
        }
    }
}

// ---------------------------------------------------------------------------
// Launch
// ---------------------------------------------------------------------------
extern "C" void kernel_launch(void* const* d_in, const int* in_sizes, int n_in,
                              void* d_out, int out_size) {
    const float* x    = (const float*)d_in[0];
    const void*  eiRaw= d_in[1];
    const float* eps0 = (const float*)d_in[2];
    const float* W1_0 = (const float*)d_in[3];
    const float* b1_0 = (const float*)d_in[4];
    const float* W2_0 = (const float*)d_in[5];
    const float* b2_0 = (const float*)d_in[6];
    const float* eps1 = (const float*)d_in[7];
    const float* W1_1 = (const float*)d_in[8];
    const float* b1_1 = (const float*)d_in[9];
    const float* W2_1 = (const float*)d_in[10];
    const float* b2_1 = (const float*)d_in[11];
    const float* Wo   = (const float*)d_in[12];
    const float* bo   = (const float*)d_in[13];
    float*       out  = (float*)d_out;

    const int two_e = in_sizes[1];
    const int E     = two_e / 2;

    float *comb, *t1, *h0, *wq;
    int *deg, *cur, *off, *esrc, *bsum, *boff;
    cudaGetSymbolAddress((void**)&comb, g_comb);
    cudaGetSymbolAddress((void**)&t1,   g_t1);
    cudaGetSymbolAddress((void**)&h0,   g_h0);
    cudaGetSymbolAddress((void**)&wq,   g_wq);
    cudaGetSymbolAddress((void**)&deg,  g_deg);
    cudaGetSymbolAddress((void**)&cur,  g_cur);
    cudaGetSymbolAddress((void**)&off,  g_off);
    cudaGetSymbolAddress((void**)&esrc, g_esrc);
    cudaGetSymbolAddress((void**)&bsum, g_bsum);
    cudaGetSymbolAddress((void**)&boff, g_boff);

    float* W1_0t = wq;                   // [256][128]
    float* W2_0t = wq + 32768;           // [256][256]
    float* W1_1t = wq + 98304;           // [256][256]
    float* W2_1t = wq + 163840;          // [256][256]
    float* Wot   = wq + 229376;          // [128][256]

    cudaFuncSetAttribute(gemm_cp<true,  true >,
                         cudaFuncAttributeMaxDynamicSharedMemorySize, GEMM_SMEM_BYTES);
    cudaFuncSetAttribute(gemm_cp<false, false>,
                         cudaFuncAttributeMaxDynamicSharedMemorySize, GEMM_SMEM_BYTES);
    cudaFuncSetAttribute(gemm_cp<false, true >,
                         cudaFuncAttributeMaxDynamicSharedMemorySize, GEMM_SMEM_BYTES);

    // ---- detect edge dtype ----
    int nscan = two_e < 128 ? two_e : 128;
    detect_kernel<<<1, 32>>>(eiRaw, nscan);

    // ---- CSR build ----
    zero_int_kernel<<<(N_NODES + 255) / 256, 256>>>(deg, N_NODES);
    hist_kernel<<<(E + 255) / 256, 256>>>(eiRaw, deg, E);
    scan_p1<<<SCAN_NB, SCAN_B>>>(deg, bsum);
    scan_p2<<<1, 256>>>(bsum, boff);
    scan_p3<<<SCAN_NB, SCAN_B>>>(deg, boff, off, cur);
    fill_kernel<<<(E + 255) / 256, 256>>>(eiRaw, cur, esrc, E);

    // ---- quantize + transpose all weights in one launch ----
    quantw_all<<<1024, 256>>>(W1_0, W2_0, W1_1, W2_1, Wo, wq);

    dim3 gH((N_NODES + 127) / 128, 2);   // Ncol=256
    dim3 gO((N_NODES + 127) / 128, 1);   // Ncol=128
    int  gGather = (N_NODES + 7) / 8;

    // ---- layer 0 ----
    gather_combine<32><<<gGather, 256>>>((const float4*)x, off, esrc, eps0, (float4*)comb);
    gemm_cp<true,  true ><<<gH, 256, GEMM_SMEM_BYTES>>>(comb, W1_0t, b1_0, t1, N_NODES, D_IN,  D_HID);
    gemm_cp<false, false><<<gH, 256, GEMM_SMEM_BYTES>>>(t1,   W2_0t, b2_0, h0, N_NODES, D_HID, D_HID);

    // ---- layer 1 ----
    gather_combine<64><<<gGather, 256>>>((const float4*)h0, off, esrc, eps1, (float4*)comb);
    gemm_cp<true,  true ><<<gH, 256, GEMM_SMEM_BYTES>>>(comb, W1_1t, b1_1, t1, N_NODES, D_HID, D_HID);
    gemm_cp<false, true ><<<gH, 256, GEMM_SMEM_BYTES>>>(t1,   W2_1t, b2_1, h0, N_NODES, D_HID, D_HID); // h1

    // ---- fc_out ----
    gemm_cp<false, false><<<gO, 256, GEMM_SMEM_BYTES>>>(h0, Wot, bo, out, N_NODES, D_HID, D_IN);
}

// round 9
// speedup vs baseline: 1.4635x; 1.4635x over previous
#include <cuda_runtime.h>
#include <cuda_fp16.h>
#include <cstdint>
#include <cstddef>

#define N_NODES 50000
#define D_IN    128
#define D_HID   256
#define E_MAX   800000

// Scratch (allocation-free rule: __device__ globals)
__device__ __half g_comb[N_NODES * D_HID];
__device__ __half g_t1 [N_NODES * D_HID];
__device__ __half g_h0 [N_NODES * D_HID];
__device__ __half g_wq [262144];            // fp16, TRANSPOSED weights [n][k]
__device__ int    g_mode;
__device__ int    g_deg [N_NODES];
__device__ int    g_cur [N_NODES];
__device__ int    g_off [N_NODES + 1];
__device__ int    g_esrc[E_MAX];
__device__ int    g_bsum[256];
__device__ int    g_boff[256];

// ---------------------------------------------------------------------------
// helpers
// ---------------------------------------------------------------------------
__device__ __forceinline__ uint32_t smem_u32(const void* p) {
    uint32_t a;
    asm("{ .reg .u64 t; cvta.to.shared.u64 t, %1; cvt.u32.u64 %0, t; }"
        : "=r"(a) : "l"(p));
    return a;
}

__device__ __forceinline__ void cpa16(uint32_t dst, const void* src, int vbytes) {
    asm volatile("cp.async.cg.shared.global [%0], [%1], 16, %2;"
                 :: "r"(dst), "l"(src), "r"(vbytes));
}
__device__ __forceinline__ void cp_commit() {
    asm volatile("cp.async.commit_group;");
}
template<int NP>
__device__ __forceinline__ void cp_wait() {
    asm volatile("cp.async.wait_group %0;" :: "n"(NP));
}

__device__ __forceinline__ void ldm4(uint32_t* r, uint32_t addr) {
    asm volatile("ldmatrix.sync.aligned.m8n8.x4.shared.b16 {%0,%1,%2,%3}, [%4];"
                 : "=r"(r[0]), "=r"(r[1]), "=r"(r[2]), "=r"(r[3]) : "r"(addr));
}

__device__ __forceinline__ void mma16(float* c, const uint32_t* a, const uint32_t* b) {
    asm volatile(
        "mma.sync.aligned.m16n8k16.row.col.f32.f16.f16.f32 "
        "{%0,%1,%2,%3}, {%4,%5,%6,%7}, {%8,%9}, {%0,%1,%2,%3};\n"
        : "+f"(c[0]), "+f"(c[1]), "+f"(c[2]), "+f"(c[3])
        : "r"(a[0]), "r"(a[1]), "r"(a[2]), "r"(a[3]), "r"(b[0]), "r"(b[1]));
}

// ---------------------------------------------------------------------------
// Edge-index dtype detect (harness may deliver int64 as int32)
// ---------------------------------------------------------------------------
__global__ void detect_kernel(const void* __restrict__ ei_raw, int nscan) {
    if (threadIdx.x == 0 && blockIdx.x == 0) {
        const long long* p = (const long long*)ei_raw;
        int is64 = 1;
        for (int i = 0; i < nscan; i++) {
            long long v = p[i];
            if (v < 0 || v >= N_NODES) { is64 = 0; break; }
        }
        g_mode = is64;
    }
}

__device__ __forceinline__ int edge_at(const void* raw, long long idx) {
    return g_mode ? (int)((const long long*)raw)[idx] : ((const int*)raw)[idx];
}

// ---------------------------------------------------------------------------
// CSR build
// ---------------------------------------------------------------------------
__global__ void zero_int_kernel(int* __restrict__ p, int n) {
    int i = blockIdx.x * blockDim.x + threadIdx.x;
    if (i < n) p[i] = 0;
}

__global__ void hist_kernel(const void* __restrict__ raw, int* __restrict__ deg, int E) {
    int e = blockIdx.x * blockDim.x + threadIdx.x;
    if (e >= E) return;
    atomicAdd(&deg[edge_at(raw, (long long)E + e)], 1);
}

#define SCAN_B 256
#define SCAN_NB ((N_NODES + SCAN_B - 1) / SCAN_B)   // 196

__global__ __launch_bounds__(SCAN_B)
void scan_p1(const int* __restrict__ deg, int* __restrict__ bsum) {
    __shared__ int sh[SCAN_B];
    int i = blockIdx.x * SCAN_B + threadIdx.x;
    sh[threadIdx.x] = (i < N_NODES) ? deg[i] : 0;
    __syncthreads();
    for (int d = SCAN_B / 2; d > 0; d >>= 1) {
        if (threadIdx.x < d) sh[threadIdx.x] += sh[threadIdx.x + d];
        __syncthreads();
    }
    if (threadIdx.x == 0) bsum[blockIdx.x] = sh[0];
}

__global__ __launch_bounds__(256)
void scan_p2(const int* __restrict__ bsum, int* __restrict__ boff) {
    __shared__ int sh[256];
    int t = threadIdx.x;
    sh[t] = (t < SCAN_NB) ? bsum[t] : 0;
    __syncthreads();
    for (int d = 1; d < 256; d <<= 1) {
        int v = (t >= d) ? sh[t - d] : 0;
        __syncthreads();
        sh[t] += v;
        __syncthreads();
    }
    if (t < SCAN_NB) boff[t] = (t == 0) ? 0 : sh[t - 1];
}

__global__ __launch_bounds__(SCAN_B)
void scan_p3(const int* __restrict__ deg, const int* __restrict__ boff,
             int* __restrict__ off, int* __restrict__ cursor) {
    __shared__ int sh[SCAN_B];
    int i = blockIdx.x * SCAN_B + threadIdx.x;
    int t = threadIdx.x;
    int v = (i < N_NODES) ? deg[i] : 0;
    sh[t] = v;
    __syncthreads();
    for (int d = 1; d < SCAN_B; d <<= 1) {
        int u = (t >= d) ? sh[t - d] : 0;
        __syncthreads();
        sh[t] += u;
        __syncthreads();
    }
    int base = boff[blockIdx.x];
    if (i < N_NODES) {
        int incl = base + sh[t];
        off[i + 1] = incl;
        cursor[i]  = incl - v;
        if (i == 0) off[0] = 0;
    }
}

__global__ void fill_kernel(const void* __restrict__ raw, int* __restrict__ cursor,
                            int* __restrict__ esrc, int E) {
    int e = blockIdx.x * blockDim.x + threadIdx.x;
    if (e >= E) return;
    int src = edge_at(raw, e);
    int dst = edge_at(raw, (long long)E + e);
    int pos = atomicAdd(&cursor[dst], 1);
    esrc[pos] = src;
}

// ---------------------------------------------------------------------------
// Weight transpose + fp16 quantize (one launch, all 5 matrices)
// dst layout per segment: [N][K], dst[n*K+k] = fp16(src[k*N+n])
// ---------------------------------------------------------------------------
__global__ void quantw_all(const float* __restrict__ w10, const float* __restrict__ w20,
                           const float* __restrict__ w11, const float* __restrict__ w21,
                           const float* __restrict__ wo,  __half* __restrict__ dst) {
    int i = blockIdx.x * blockDim.x + threadIdx.x;
    if (i >= 262144) return;
    const float* src;
    int d, K, N;
    if      (i < 32768)  { src = w10; d = i;          K = 128; N = 256; }
    else if (i < 98304)  { src = w20; d = i - 32768;  K = 256; N = 256; }
    else if (i < 163840) { src = w11; d = i - 98304;  K = 256; N = 256; }
    else if (i < 229376) { src = w21; d = i - 163840; K = 256; N = 256; }
    else                 { src = wo;  d = i - 229376; K = 256; N = 128; }
    int n = d / K, k = d - n * K;
    dst[i] = __float2half_rn(src[(size_t)k * N + n]);
}

// ---------------------------------------------------------------------------
// Gather + GIN combine, layer 0: fp32 input x -> fp16 comb
// One warp per node; lane covers 4 floats (float4 at idx lane).
// ---------------------------------------------------------------------------
__device__ __forceinline__ void f4add(float4& a, const float4& b) {
    a.x += b.x; a.y += b.y; a.z += b.z; a.w += b.w;
}

__global__ __launch_bounds__(256)
void gather_combine_f32(const float4* __restrict__ x,
                        const int* __restrict__ off,
                        const int* __restrict__ esrc,
                        const float* __restrict__ epsp,
                        __half* __restrict__ out) {
    int node = blockIdx.x * 8 + (threadIdx.x >> 5);
    if (node >= N_NODES) return;
    int lane = threadIdx.x & 31;
    float scale = 1.f + __ldg(epsp);
    int s = off[node], e = off[node + 1];

    float4 a0 = make_float4(0.f, 0.f, 0.f, 0.f);
    int i = s;
    for (; i + 1 < e; i += 2) {
        f4add(a0, __ldg(x + (size_t)esrc[i]     * 32 + lane));
        f4add(a0, __ldg(x + (size_t)esrc[i + 1] * 32 + lane));
    }
    if (i < e) f4add(a0, __ldg(x + (size_t)esrc[i] * 32 + lane));
    {
        float4 v = __ldg(x + (size_t)node * 32 + lane);
        a0.x = fmaf(scale, v.x, a0.x);
        a0.y = fmaf(scale, v.y, a0.y);
        a0.z = fmaf(scale, v.z, a0.z);
        a0.w = fmaf(scale, v.w, a0.w);
    }
    __half2 h0 = __floats2half2_rn(a0.x, a0.y);
    __half2 h1 = __floats2half2_rn(a0.z, a0.w);
    uint2 pk = make_uint2(*(uint32_t*)&h0, *(uint32_t*)&h1);
    *reinterpret_cast<uint2*>(out + (size_t)node * 128 + lane * 4) = pk;
}

// ---------------------------------------------------------------------------
// Gather + GIN combine, layer 1: fp16 input h0 (256 cols) -> fp16 comb
// One warp per node; lane covers 8 halves (uint4 at idx lane).
// ---------------------------------------------------------------------------
__device__ __forceinline__ void h8_acc(float* acc, uint4 v) {
    const __half2* hp = reinterpret_cast<const __half2*>(&v);
    #pragma unroll
    for (int j = 0; j < 4; j++) {
        float2 f = __half22float2(hp[j]);
        acc[2 * j]     += f.x;
        acc[2 * j + 1] += f.y;
    }
}

__global__ __launch_bounds__(256)
void gather_combine_f16(const uint4* __restrict__ x,   // h0 as uint4 rows of 32
                        const int* __restrict__ off,
                        const int* __restrict__ esrc,
                        const float* __restrict__ epsp,
                        __half* __restrict__ out) {
    int node = blockIdx.x * 8 + (threadIdx.x >> 5);
    if (node >= N_NODES) return;
    int lane = threadIdx.x & 31;
    float scale = 1.f + __ldg(epsp);
    int s = off[node], e = off[node + 1];

    float acc[8];
    #pragma unroll
    for (int j = 0; j < 8; j++) acc[j] = 0.f;

    int i = s;
    for (; i + 1 < e; i += 2) {
        uint4 v0 = __ldg(x + (size_t)esrc[i]     * 32 + lane);
        uint4 v1 = __ldg(x + (size_t)esrc[i + 1] * 32 + lane);
        h8_acc(acc, v0);
        h8_acc(acc, v1);
    }
    if (i < e) {
        uint4 v0 = __ldg(x + (size_t)esrc[i] * 32 + lane);
        h8_acc(acc, v0);
    }
    {
        uint4 v = __ldg(x + (size_t)node * 32 + lane);
        const __half2* hp = reinterpret_cast<const __half2*>(&v);
        #pragma unroll
        for (int j = 0; j < 4; j++) {
            float2 f = __half22float2(hp[j]);
            acc[2 * j]     = fmaf(scale, f.x, acc[2 * j]);
            acc[2 * j + 1] = fmaf(scale, f.y, acc[2 * j + 1]);
        }
    }
    uint4 pk;
    __half2 p0 = __floats2half2_rn(acc[0], acc[1]);
    __half2 p1 = __floats2half2_rn(acc[2], acc[3]);
    __half2 p2 = __floats2half2_rn(acc[4], acc[5]);
    __half2 p3 = __floats2half2_rn(acc[6], acc[7]);
    pk.x = *(uint32_t*)&p0; pk.y = *(uint32_t*)&p1;
    pk.z = *(uint32_t*)&p2; pk.w = *(uint32_t*)&p3;
    *reinterpret_cast<uint4*>(out + (size_t)node * 256 + lane * 8) = pk;
}

// ---------------------------------------------------------------------------
// FP16 mma.sync GEMM (m16n8k16), ldmatrix fragments, 3-stage cp.async.
//   C = op(A @ Wt^T + bias);  BM=128, BN=128, BK=32; 256 thr (4m x 2n warps).
//   A smem [m][32 halves], row pitch 80B (pad) -> ldmatrix conflict-free.
//   B smem [n][32 halves], same pitch (Wt is [n][k]).
// ---------------------------------------------------------------------------
#define APITCH   80                         // bytes per smem row (64 data + 16 pad)
#define ASTG_B   (128 * APITCH)             // 10240 bytes
#define STG_B    (2 * ASTG_B)               // A + B per stage
#define GEMM_SMEM_BYTES (3 * STG_B)         // 61440

template<bool RELU, bool OUT16>
__global__ __launch_bounds__(256, 2)
void gemm_fp16(const __half* __restrict__ A,
               const __half* __restrict__ Wt,     // [Ntot][K]
               const float* __restrict__ bias,
               void* __restrict__ Cv,
               int M, int K, int Ncol) {
    extern __shared__ char dsm[];
    const uint32_t sbase = smem_u32(dsm);

    const int tid  = threadIdx.x;
    const int lane = tid & 31;
    const int warp = tid >> 5;
    const int wm   = warp >> 1;        // 0..3
    const int wn   = warp & 1;         // 0..1
    const int gid  = lane >> 2;        // 0..7
    const int tig  = lane & 3;         // 0..3

    const int row0 = blockIdx.x * 128;
    const int col0 = blockIdx.y * 128;

    float acc[2][8][4];
    #pragma unroll
    for (int mt = 0; mt < 2; mt++)
        #pragma unroll
        for (int nt = 0; nt < 8; nt++)
            #pragma unroll
            for (int i = 0; i < 4; i++)
                acc[mt][nt][i] = 0.f;

    // ldmatrix per-lane source offsets (within a stage)
    const int a_lrow = lane & 15;                 // row within 16-row frag
    const int a_kext = (lane & 16) ? 16 : 0;      // +16B for k8-15 matrices
    const int b_lrow = (lane & 7) + ((lane & 16) ? 8 : 0);
    const int b_kext = (lane & 8) ? 16 : 0;

    auto issue = [&](int c) {
        const int k0  = c * 32;                   // in halves
        const int stg = c % 3;
        const uint32_t abase = sbase + stg * STG_B;
        #pragma unroll
        for (int i = 0; i < 2; i++) {
            int chunk = tid + 256 * i;            // 0..511
            int row = chunk >> 2, cs = chunk & 3; // cs: 8-half span
            bool ok = (row0 + row) < M;
            const __half* src = ok ? (A + (size_t)(row0 + row) * K + k0 + cs * 8) : A;
            cpa16(abase + row * APITCH + cs * 16, src, ok ? 16 : 0);
        }
        const uint32_t bbase = abase + ASTG_B;
        #pragma unroll
        for (int i = 0; i < 2; i++) {
            int chunk = tid + 256 * i;
            int n = chunk >> 2, cs = chunk & 3;
            const __half* src = Wt + (size_t)(col0 + n) * K + k0 + cs * 8;
            cpa16(bbase + n * APITCH + cs * 16, src, 16);
        }
    };

    auto compute = [&](int c) {
        const int stg = c % 3;
        const uint32_t abase = sbase + stg * STG_B;
        const uint32_t bbase = abase + ASTG_B;
        #pragma unroll
        for (int ks = 0; ks < 2; ks++) {
            uint32_t af[2][4];
            #pragma unroll
            for (int mt = 0; mt < 2; mt++) {
                int r = wm * 32 + mt * 16 + a_lrow;
                ldm4(af[mt], abase + r * APITCH + ks * 32 + a_kext);
            }
            uint32_t bf[8][2];
            #pragma unroll
            for (int np = 0; np < 4; np++) {
                int n = wn * 64 + np * 16 + b_lrow;
                uint32_t r4[4];
                ldm4(r4, bbase + n * APITCH + ks * 32 + b_kext);
                bf[2 * np][0]     = r4[0];
                bf[2 * np][1]     = r4[1];
                bf[2 * np + 1][0] = r4[2];
                bf[2 * np + 1][1] = r4[3];
            }
            #pragma unroll
            for (int mt = 0; mt < 2; mt++)
                #pragma unroll
                for (int nt = 0; nt < 8; nt++)
                    mma16(acc[mt][nt], af[mt], bf[nt]);
        }
    };

    const int NC = K / 32;
    issue(0); cp_commit();
    issue(1); cp_commit();

    for (int c = 0; c < NC; c++) {
        cp_wait<1>();
        __syncthreads();
        if (c + 2 < NC) issue(c + 2);
        cp_commit();
        compute(c);
    }

    // ---- epilogue ----
    #pragma unroll
    for (int nt = 0; nt < 8; nt++) {
        int col = col0 + wn * 64 + nt * 8 + 2 * tig;
        float b0 = __ldg(bias + col);
        float b1 = __ldg(bias + col + 1);
        #pragma unroll
        for (int mt = 0; mt < 2; mt++) {
            int r = row0 + wm * 32 + mt * 16 + gid;
            float v0 = acc[mt][nt][0] + b0;
            float v1 = acc[mt][nt][1] + b1;
            float v2 = acc[mt][nt][2] + b0;
            float v3 = acc[mt][nt][3] + b1;
            if (RELU) {
                v0 = fmaxf(v0, 0.f); v1 = fmaxf(v1, 0.f);
                v2 = fmaxf(v2, 0.f); v3 = fmaxf(v3, 0.f);
            }
            if (OUT16) {
                __half* C = (__half*)Cv;
                if (r < M) {
                    __half2 h = __floats2half2_rn(v0, v1);
                    *reinterpret_cast<__half2*>(C + (size_t)r * Ncol + col) = h;
                }
                if (r + 8 < M) {
                    __half2 h = __floats2half2_rn(v2, v3);
                    *reinterpret_cast<__half2*>(C + (size_t)(r + 8) * Ncol + col) = h;
                }
            } else {
                float* C = (float*)Cv;
                if (r < M)
                    *reinterpret_cast<float2*>(C + (size_t)r * Ncol + col) = make_float2(v0, v1);
                if (r + 8 < M)
                    *reinterpret_cast<float2*>(C + (size_t)(r + 8) * Ncol + col) = make_float2(v2, v3);
            }
        }
    }
}

// ---------------------------------------------------------------------------
// Launch
// ---------------------------------------------------------------------------
extern "C" void kernel_launch(void* const* d_in, const int* in_sizes, int n_in,
                              void* d_out, int out_size) {
    const float* x    = (const float*)d_in[0];
    const void*  eiRaw= d_in[1];
    const float* eps0 = (const float*)d_in[2];
    const float* W1_0 = (const float*)d_in[3];
    const float* b1_0 = (const float*)d_in[4];
    const float* W2_0 = (const float*)d_in[5];
    const float* b2_0 = (const float*)d_in[6];
    const float* eps1 = (const float*)d_in[7];
    const float* W1_1 = (const float*)d_in[8];
    const float* b1_1 = (const float*)d_in[9];
    const float* W2_1 = (const float*)d_in[10];
    const float* b2_1 = (const float*)d_in[11];
    const float* Wo   = (const float*)d_in[12];
    const float* bo   = (const float*)d_in[13];
    float*       out  = (float*)d_out;

    const int two_e = in_sizes[1];
    const int E     = two_e / 2;

    __half *comb, *t1, *h0, *wq;
    int *deg, *cur, *off, *esrc, *bsum, *boff;
    cudaGetSymbolAddress((void**)&comb, g_comb);
    cudaGetSymbolAddress((void**)&t1,   g_t1);
    cudaGetSymbolAddress((void**)&h0,   g_h0);
    cudaGetSymbolAddress((void**)&wq,   g_wq);
    cudaGetSymbolAddress((void**)&deg,  g_deg);
    cudaGetSymbolAddress((void**)&cur,  g_cur);
    cudaGetSymbolAddress((void**)&off,  g_off);
    cudaGetSymbolAddress((void**)&esrc, g_esrc);
    cudaGetSymbolAddress((void**)&bsum, g_bsum);
    cudaGetSymbolAddress((void**)&boff, g_boff);

    __half* W1_0t = wq;                   // [256][128]
    __half* W2_0t = wq + 32768;           // [256][256]
    __half* W1_1t = wq + 98304;           // [256][256]
    __half* W2_1t = wq + 163840;          // [256][256]
    __half* Wot   = wq + 229376;          // [128][256]

    cudaFuncSetAttribute(gemm_fp16<true,  true >,
                         cudaFuncAttributeMaxDynamicSharedMemorySize, GEMM_SMEM_BYTES);
    cudaFuncSetAttribute(gemm_fp16<false, true >,
                         cudaFuncAttributeMaxDynamicSharedMemorySize, GEMM_SMEM_BYTES);
    cudaFuncSetAttribute(gemm_fp16<false, false>,
                         cudaFuncAttributeMaxDynamicSharedMemorySize, GEMM_SMEM_BYTES);

    // ---- detect edge dtype ----
    int nscan = two_e < 128 ? two_e : 128;
    detect_kernel<<<1, 32>>>(eiRaw, nscan);

    // ---- CSR build ----
    zero_int_kernel<<<(N_NODES + 255) / 256, 256>>>(deg, N_NODES);
    hist_kernel<<<(E + 255) / 256, 256>>>(eiRaw, deg, E);
    scan_p1<<<SCAN_NB, SCAN_B>>>(deg, bsum);
    scan_p2<<<1, 256>>>(bsum, boff);
    scan_p3<<<SCAN_NB, SCAN_B>>>(deg, boff, off, cur);
    fill_kernel<<<(E + 255) / 256, 256>>>(eiRaw, cur, esrc, E);

    // ---- quantize + transpose all weights in one launch ----
    quantw_all<<<1024, 256>>>(W1_0, W2_0, W1_1, W2_1, Wo, wq);

    dim3 gH((N_NODES + 127) / 128, 2);   // Ncol=256
    dim3 gO((N_NODES + 127) / 128, 1);   // Ncol=128
    int  gGather = (N_NODES + 7) / 8;

    // ---- layer 0 ----
    gather_combine_f32<<<gGather, 256>>>((const float4*)x, off, esrc, eps0, comb);
    gemm_fp16<true,  true ><<<gH, 256, GEMM_SMEM_BYTES>>>(comb, W1_0t, b1_0, t1, N_NODES, D_IN,  D_HID);
    gemm_fp16<false, true ><<<gH, 256, GEMM_SMEM_BYTES>>>(t1,   W2_0t, b2_0, h0, N_NODES, D_HID, D_HID);

    // ---- layer 1 ----
    gather_combine_f16<<<gGather, 256>>>((const uint4*)h0, off, esrc, eps1, comb);
    gemm_fp16<true,  true ><<<gH, 256, GEMM_SMEM_BYTES>>>(comb, W1_1t, b1_1, t1, N_NODES, D_HID, D_HID);
    gemm_fp16<false, true ><<<gH, 256, GEMM_SMEM_BYTES>>>(t1,   W2_1t, b2_1, h0, N_NODES, D_HID, D_HID); // h1

    // ---- fc_out (fp32 out) ----
    gemm_fp16<false, false><<<gO, 256, GEMM_SMEM_BYTES>>>(h0, Wot, bo, out, N_NODES, D_HID, D_IN);
}